// round 8
// baseline (speedup 1.0000x reference)
#include <cuda_runtime.h>
#include <cuda_bf16.h>
#include <cstdint>

#define B_ 16
#define T_ 4096
#define D_ 512
#define R_ 256

// ---------------- scratch (device globals; no allocation allowed) ----------------
__device__ float g_Qf[(size_t)B_ * T_ * D_];   // normalized z, full fp32 (128 MB)
__device__ float g_Kf[(size_t)B_ * R_ * D_];   // gathered landmark rows (8 MB)
__device__ float g_W [(size_t)T_ * R_];        // mask * exp(-a*tdist)  (4 MB)
__device__ int   g_lm[R_];
__device__ float g_alpha[3];
__device__ float g_atd;

// split x = hi + lo, both tf32-representable (3xTF32 emulation)
__device__ __forceinline__ void tf32_split(float x, uint32_t& hi, uint32_t& lo) {
    asm("cvt.rna.tf32.f32 %0, %1;" : "=r"(hi) : "f"(x));
    float res = x - __uint_as_float(hi);
    asm("cvt.rna.tf32.f32 %0, %1;" : "=r"(lo) : "f"(res));
}

// ---------------- kernel 1: scalars + landmarks ----------------
__global__ void prep_kernel(const float* __restrict__ gw, const float* __restrict__ ta) {
    int i = threadIdx.x;
    if (i < R_) {
        // replicate numpy linspace(0,4095,256).astype(int64) exactly
        double delta = 4095.0 / 255.0;
        long long v = (long long)((double)i * delta);
        if (i == R_ - 1) v = 4095;
        g_lm[i] = (int)v;
    }
    if (i == 0) {
        float w0 = gw[0], w1 = gw[1], w2 = gw[2];
        float m = fmaxf(w0, fmaxf(w1, w2));
        float e0 = expf(w0 - m), e1 = expf(w1 - m), e2 = expf(w2 - m);
        float s = e0 + e1 + e2;
        g_alpha[0] = e0 / s; g_alpha[1] = e1 / s; g_alpha[2] = e2 / s;
        float x = ta[0];                                   // softplus = logaddexp(x,0)
        g_atd = fmaxf(x, 0.0f) + log1pf(expf(-fabsf(x)));
    }
}

// ---------------- kernel 2: W[t][r] = mask * exp(-a*tdist) ----------------
__global__ void w_kernel() {
    int t = blockIdx.x;          // 0..4095
    int r = threadIdx.x;         // 0..255
    int lm = g_lm[r];
    float w = 0.0f;
    if (lm < t) {
        float td = ((float)t - (float)lm) * (1.0f / 4096.0f);  // exact (pow2 divide)
        w = expf(-g_atd * td);
    }
    g_W[(size_t)t * R_ + r] = w;
}

// ---------------- kernel 3: normalize rows of z -> fp32 Q ----------------
__global__ void norm_kernel(const float* __restrict__ z) {
    int row = blockIdx.x;                 // 0 .. B*T-1
    size_t base = (size_t)row * D_;
    int tid = threadIdx.x;                // 128 threads, 4 floats each
    float4 v = reinterpret_cast<const float4*>(z + base)[tid];
    float ss = v.x * v.x + v.y * v.y + v.z * v.z + v.w * v.w;
    #pragma unroll
    for (int o = 16; o > 0; o >>= 1) ss += __shfl_xor_sync(0xffffffffu, ss, o);
    __shared__ float ws[4];
    if ((tid & 31) == 0) ws[tid >> 5] = ss;
    __syncthreads();
    float tot = ws[0] + ws[1] + ws[2] + ws[3];
    float inv = 1.0f / fmaxf(sqrtf(tot), 1e-12f);
    float4 q;
    q.x = v.x * inv; q.y = v.y * inv;
    q.z = v.z * inv; q.w = v.w * inv;
    reinterpret_cast<float4*>(g_Qf + base)[tid] = q;
}

// ---------------- kernel 4: gather landmark rows into K ----------------
__global__ void gather_kernel() {
    int rowid = blockIdx.x;               // b*R + r
    int b = rowid >> 8, r = rowid & 255;
    int lm = g_lm[r];
    const float4* src = reinterpret_cast<const float4*>(g_Qf + ((size_t)(b * T_ + lm)) * D_);
    float4* dst = reinterpret_cast<float4*>(g_Kf + (size_t)rowid * D_);
    dst[threadIdx.x] = src[threadIdx.x];  // 128 threads * 16B = 2KB row
}

// ---------------- kernel 5: fused GEMM + epilogue (3xTF32) ----------------
#define BM 64
#define BN 256
#define BK 16
#define ASTR 20                       /* 16 + 4 pad floats: conflict-free frag LDS */
#define A_TILE (BM * ASTR)            /* 1280 floats */
#define B_TILE (BN * ASTR)            /* 5120 floats */
#define SMEM_BYTES (2 * (A_TILE + B_TILE) * 4)   /* 51200 B */

__device__ __forceinline__ void cp16(float* sdst, const float* gsrc) {
    uint32_t s = (uint32_t)__cvta_generic_to_shared(sdst);
    asm volatile("cp.async.cg.shared.global [%0], [%1], 16;" :: "r"(s), "l"(gsrc));
}

__device__ __forceinline__ void mma_tf32(float* acc,
                                         uint32_t a0, uint32_t a1, uint32_t a2, uint32_t a3,
                                         uint32_t b0, uint32_t b1) {
    asm volatile(
        "mma.sync.aligned.m16n8k8.row.col.f32.tf32.tf32.f32 "
        "{%0,%1,%2,%3}, {%4,%5,%6,%7}, {%8,%9}, {%0,%1,%2,%3};"
        : "+f"(acc[0]), "+f"(acc[1]), "+f"(acc[2]), "+f"(acc[3])
        : "r"(a0), "r"(a1), "r"(a2), "r"(a3), "r"(b0), "r"(b1));
}

__device__ __forceinline__ float gphi(float C, float A0, float A1, float A2) {
    float C2 = C * C;
    float P1 = 0.5f * (1.0f + C);
    float P2 = 0.5f * (3.0f * C2 - 1.0f);
    float P3 = 0.5f * (5.0f * C2 * C - 3.0f * C);
    return A0 * P1 + A1 * P2 + A2 * P3;
}

__global__ void __launch_bounds__(256) gemm_kernel(float* __restrict__ out) {
    extern __shared__ float sm[];
    float* As = sm;                     // [2][BM][ASTR]
    float* Bs = sm + 2 * A_TILE;        // [2][BN][ASTR]

    int tid = threadIdx.x;
    int b  = blockIdx.y;
    int t0 = blockIdx.x * BM;
    const float* Ag = g_Qf + ((size_t)b * T_ + t0) * D_;
    const float* Bg = g_Kf + (size_t)b * R_ * D_;

    int warp = tid >> 5, lane = tid & 31;
    int wm = warp >> 1, wn = warp & 1;    // 4 x 2 warp grid: 16 rows x 128 cols each
    int r4 = lane >> 2, c4 = lane & 3;

    float acc[16][4];
    #pragma unroll
    for (int j = 0; j < 16; j++) { acc[j][0] = 0.f; acc[j][1] = 0.f; acc[j][2] = 0.f; acc[j][3] = 0.f; }

    int arow = tid >> 2, acol = (tid & 3) * 4;   // A: 256 chunks of 16B -> 1/thread

    // prefetch k-tile 0
    cp16(&As[arow * ASTR + acol], Ag + (size_t)arow * D_ + acol);
    #pragma unroll
    for (int i = 0; i < 4; i++) {                // B: 1024 chunks -> 4/thread
        int c = tid + i * 256; int row = c >> 2, col = (c & 3) * 4;
        cp16(&Bs[row * ASTR + col], Bg + (size_t)row * D_ + col);
    }
    asm volatile("cp.async.commit_group;");

    const int KI = D_ / BK;   // 32
    for (int kt = 0; kt < KI; kt++) {
        int buf = kt & 1;
        if (kt + 1 < KI) {
            int nb = buf ^ 1; int k0 = (kt + 1) * BK;
            cp16(&As[nb * A_TILE + arow * ASTR + acol], Ag + (size_t)arow * D_ + k0 + acol);
            #pragma unroll
            for (int i = 0; i < 4; i++) {
                int c = tid + i * 256; int row = c >> 2, col = (c & 3) * 4;
                cp16(&Bs[nb * B_TILE + row * ASTR + col], Bg + (size_t)row * D_ + k0 + col);
            }
            asm volatile("cp.async.commit_group;");
            asm volatile("cp.async.wait_group 1;");
        } else {
            asm volatile("cp.async.wait_group 0;");
        }
        __syncthreads();

        const float* __restrict__ Ab = As + buf * A_TILE + (wm * 16) * ASTR;
        const float* __restrict__ Bb = Bs + buf * B_TILE + (wn * 128) * ASTR;
        #pragma unroll
        for (int s = 0; s < 2; s++) {           // two k8 steps per BK=16
            int kc = s * 8 + c4;
            // A fragment: split into tf32 hi/lo (hoisted above j-loop)
            uint32_t ah[4], al[4];
            tf32_split(Ab[r4 * ASTR + kc],            ah[0], al[0]);
            tf32_split(Ab[(r4 + 8) * ASTR + kc],      ah[1], al[1]);
            tf32_split(Ab[r4 * ASTR + kc + 4],        ah[2], al[2]);
            tf32_split(Ab[(r4 + 8) * ASTR + kc + 4],  ah[3], al[3]);
            // Split all B fragments first, then issue MMAs grouped by term so
            // RAW chains on acc[j] are interleaved across independent j's.
            uint32_t bh0[16], bl0[16], bh1[16], bl1[16];
            #pragma unroll
            for (int j = 0; j < 16; j++) {
                tf32_split(Bb[(j * 8 + r4) * ASTR + kc],     bh0[j], bl0[j]);
                tf32_split(Bb[(j * 8 + r4) * ASTR + kc + 4], bh1[j], bl1[j]);
            }
            #pragma unroll
            for (int j = 0; j < 16; j++)   // hi * hi
                mma_tf32(acc[j], ah[0], ah[1], ah[2], ah[3], bh0[j], bh1[j]);
            #pragma unroll
            for (int j = 0; j < 16; j++)   // hi * lo
                mma_tf32(acc[j], ah[0], ah[1], ah[2], ah[3], bl0[j], bl1[j]);
            #pragma unroll
            for (int j = 0; j < 16; j++)   // lo * hi
                mma_tf32(acc[j], al[0], al[1], al[2], al[3], bh0[j], bh1[j]);
        }
        __syncthreads();
    }

    // ---------------- fused epilogue ----------------
    float A0 = g_alpha[0], A1 = g_alpha[1], A2 = g_alpha[2];
    int gr0 = t0 + wm * 16 + r4;     // global t of this thread's first row
    int gr1 = gr0 + 8;
    const float* W0 = g_W + (size_t)gr0 * R_;
    const float* W1 = g_W + (size_t)gr1 * R_;

    float s0 = 0.f, s1 = 0.f;
    #pragma unroll
    for (int j = 0; j < 16; j++) {
        int col = wn * 128 + j * 8 + c4 * 2;
        float p;
        p = gphi(acc[j][0], A0, A1, A2) * W0[col];     acc[j][0] = p; s0 += p;
        p = gphi(acc[j][1], A0, A1, A2) * W0[col + 1]; acc[j][1] = p; s0 += p;
        p = gphi(acc[j][2], A0, A1, A2) * W1[col];     acc[j][2] = p; s1 += p;
        p = gphi(acc[j][3], A0, A1, A2) * W1[col + 1]; acc[j][3] = p; s1 += p;
    }
    // reduce across the 4 lanes sharing a row
    s0 += __shfl_xor_sync(0xffffffffu, s0, 1);
    s0 += __shfl_xor_sync(0xffffffffu, s0, 2);
    s1 += __shfl_xor_sync(0xffffffffu, s1, 1);
    s1 += __shfl_xor_sync(0xffffffffu, s1, 2);

    // reduce across the two warp_n halves
    __shared__ float red[4][2][16];
    if (c4 == 0) { red[wm][wn][r4] = s0; red[wm][wn][r4 + 8] = s1; }
    __syncthreads();
    float inv0 = 1.0f / fmaxf(red[wm][0][r4]     + red[wm][1][r4],     1e-6f);
    float inv1 = 1.0f / fmaxf(red[wm][0][r4 + 8] + red[wm][1][r4 + 8], 1e-6f);

    float* o0 = out + ((size_t)b * T_ + gr0) * (R_ + 1);
    float* o1 = out + ((size_t)b * T_ + gr1) * (R_ + 1);
    #pragma unroll
    for (int j = 0; j < 16; j++) {
        int col = wn * 128 + j * 8 + c4 * 2;
        o0[col]     = acc[j][0] * inv0;
        o0[col + 1] = acc[j][1] * inv0;
        o1[col]     = acc[j][2] * inv1;
        o1[col + 1] = acc[j][3] * inv1;
    }
    if (wn == 0 && c4 == 0) { o0[R_] = 1.0f; o1[R_] = 1.0f; }
}

// ---------------- launch ----------------
extern "C" void kernel_launch(void* const* d_in, const int* in_sizes, int n_in,
                              void* d_out, int out_size) {
    const float* z  = (const float*)d_in[0];
    const float* gw = (const float*)d_in[1];
    const float* ta = (const float*)d_in[2];
    float* out = (float*)d_out;

    prep_kernel<<<1, 256>>>(gw, ta);
    w_kernel<<<T_, R_>>>();
    norm_kernel<<<B_ * T_, 128>>>(z);
    gather_kernel<<<B_ * R_, 128>>>();

    cudaFuncSetAttribute(gemm_kernel, cudaFuncAttributeMaxDynamicSharedMemorySize, SMEM_BYTES);
    gemm_kernel<<<dim3(T_ / BM, B_), 256, SMEM_BYTES>>>(out);
}

// round 10
// speedup vs baseline: 1.0640x; 1.0640x over previous
#include <cuda_runtime.h>
#include <cuda_bf16.h>
#include <cstdint>

#define B_ 16
#define T_ 4096
#define D_ 512
#define R_ 256

// ---------------- scratch (device globals; no allocation allowed) ----------------
__device__ float g_Qf [(size_t)B_ * T_ * D_];  // normalized z, full fp32 (128 MB)
__device__ float g_Khi[(size_t)B_ * R_ * D_];  // landmark rows, tf32 hi (8 MB)
__device__ float g_Klo[(size_t)B_ * R_ * D_];  // landmark rows, tf32 lo (8 MB)
__device__ float g_W  [(size_t)T_ * R_];       // mask * exp(-a*tdist)  (4 MB)
__device__ int   g_lm[R_];
__device__ float g_alpha[3];
__device__ float g_atd;

// split x = hi + lo, both tf32-representable (3xTF32 emulation)
__device__ __forceinline__ void tf32_split(float x, uint32_t& hi, uint32_t& lo) {
    asm("cvt.rna.tf32.f32 %0, %1;" : "=r"(hi) : "f"(x));
    float res = x - __uint_as_float(hi);
    asm("cvt.rna.tf32.f32 %0, %1;" : "=r"(lo) : "f"(res));
}

// ---------------- kernel 1: scalars + landmarks ----------------
__global__ void prep_kernel(const float* __restrict__ gw, const float* __restrict__ ta) {
    int i = threadIdx.x;
    if (i < R_) {
        // replicate numpy linspace(0,4095,256).astype(int64) exactly
        double delta = 4095.0 / 255.0;
        long long v = (long long)((double)i * delta);
        if (i == R_ - 1) v = 4095;
        g_lm[i] = (int)v;
    }
    if (i == 0) {
        float w0 = gw[0], w1 = gw[1], w2 = gw[2];
        float m = fmaxf(w0, fmaxf(w1, w2));
        float e0 = expf(w0 - m), e1 = expf(w1 - m), e2 = expf(w2 - m);
        float s = e0 + e1 + e2;
        g_alpha[0] = e0 / s; g_alpha[1] = e1 / s; g_alpha[2] = e2 / s;
        float x = ta[0];                                   // softplus = logaddexp(x,0)
        g_atd = fmaxf(x, 0.0f) + log1pf(expf(-fabsf(x)));
    }
}

// ---------------- kernel 2: W[t][r] = mask * exp(-a*tdist) ----------------
__global__ void w_kernel() {
    int t = blockIdx.x;          // 0..4095
    int r = threadIdx.x;         // 0..255
    int lm = g_lm[r];
    float w = 0.0f;
    if (lm < t) {
        float td = ((float)t - (float)lm) * (1.0f / 4096.0f);  // exact (pow2 divide)
        w = expf(-g_atd * td);
    }
    g_W[(size_t)t * R_ + r] = w;
}

// ---------------- kernel 3: normalize rows of z -> fp32 Q ----------------
__global__ void norm_kernel(const float* __restrict__ z) {
    int row = blockIdx.x;                 // 0 .. B*T-1
    size_t base = (size_t)row * D_;
    int tid = threadIdx.x;                // 128 threads, 4 floats each
    float4 v = reinterpret_cast<const float4*>(z + base)[tid];
    float ss = v.x * v.x + v.y * v.y + v.z * v.z + v.w * v.w;
    #pragma unroll
    for (int o = 16; o > 0; o >>= 1) ss += __shfl_xor_sync(0xffffffffu, ss, o);
    __shared__ float ws[4];
    if ((tid & 31) == 0) ws[tid >> 5] = ss;
    __syncthreads();
    float tot = ws[0] + ws[1] + ws[2] + ws[3];
    float inv = 1.0f / fmaxf(sqrtf(tot), 1e-12f);
    float4 q;
    q.x = v.x * inv; q.y = v.y * inv;
    q.z = v.z * inv; q.w = v.w * inv;
    reinterpret_cast<float4*>(g_Qf + base)[tid] = q;
}

// ---------------- kernel 4: gather + pre-split landmark rows ----------------
__global__ void gather_kernel() {
    int rowid = blockIdx.x;               // b*R + r
    int b = rowid >> 8, r = rowid & 255;
    int lm = g_lm[r];
    const float4* src = reinterpret_cast<const float4*>(g_Qf + ((size_t)(b * T_ + lm)) * D_);
    float4 v = src[threadIdx.x];          // 128 threads * 16B = 2KB row
    float4 h, l;
    uint32_t hu, lu;
    tf32_split(v.x, hu, lu); h.x = __uint_as_float(hu); l.x = __uint_as_float(lu);
    tf32_split(v.y, hu, lu); h.y = __uint_as_float(hu); l.y = __uint_as_float(lu);
    tf32_split(v.z, hu, lu); h.z = __uint_as_float(hu); l.z = __uint_as_float(lu);
    tf32_split(v.w, hu, lu); h.w = __uint_as_float(hu); l.w = __uint_as_float(lu);
    reinterpret_cast<float4*>(g_Khi + (size_t)rowid * D_)[threadIdx.x] = h;
    reinterpret_cast<float4*>(g_Klo + (size_t)rowid * D_)[threadIdx.x] = l;
}

// ---------------- kernel 5: fused GEMM + epilogue (3xTF32, pre-split K) ------
#define BM 64
#define BN 256
#define BK 16
#define ASTR 20                       /* 16 + 4 pad floats: conflict-free frag LDS */
#define A_TILE (BM * ASTR)            /* 1280 floats */
#define B_TILE (BN * ASTR)            /* 5120 floats */
/* per buffer: A + Bhi + Blo */
#define BUF_SZ (A_TILE + 2 * B_TILE)  /* 11520 floats */
#define SMEM_BYTES (2 * BUF_SZ * 4)   /* 92160 B */

__device__ __forceinline__ void cp16(float* sdst, const float* gsrc) {
    uint32_t s = (uint32_t)__cvta_generic_to_shared(sdst);
    asm volatile("cp.async.cg.shared.global [%0], [%1], 16;" :: "r"(s), "l"(gsrc));
}

__device__ __forceinline__ void mma_tf32(float* acc,
                                         uint32_t a0, uint32_t a1, uint32_t a2, uint32_t a3,
                                         uint32_t b0, uint32_t b1) {
    asm volatile(
        "mma.sync.aligned.m16n8k8.row.col.f32.tf32.tf32.f32 "
        "{%0,%1,%2,%3}, {%4,%5,%6,%7}, {%8,%9}, {%0,%1,%2,%3};"
        : "+f"(acc[0]), "+f"(acc[1]), "+f"(acc[2]), "+f"(acc[3])
        : "r"(a0), "r"(a1), "r"(a2), "r"(a3), "r"(b0), "r"(b1));
}

__device__ __forceinline__ float gphi(float C, float A0, float A1, float A2) {
    float C2 = C * C;
    float P1 = 0.5f * (1.0f + C);
    float P2 = 0.5f * (3.0f * C2 - 1.0f);
    float P3 = 0.5f * (5.0f * C2 * C - 3.0f * C);
    return A0 * P1 + A1 * P2 + A2 * P3;
}

__global__ void __launch_bounds__(256) gemm_kernel(float* __restrict__ out) {
    extern __shared__ float sm[];
    // layout per buffer: [A_TILE | Bhi_TILE | Blo_TILE]
    int tid = threadIdx.x;
    int b  = blockIdx.y;
    int t0 = blockIdx.x * BM;
    const float* Ag  = g_Qf  + ((size_t)b * T_ + t0) * D_;
    const float* Bhg = g_Khi + (size_t)b * R_ * D_;
    const float* Blg = g_Klo + (size_t)b * R_ * D_;

    int warp = tid >> 5, lane = tid & 31;
    int wm = warp >> 1, wn = warp & 1;    // 4 x 2 warp grid: 16 rows x 128 cols each
    int r4 = lane >> 2, c4 = lane & 3;

    float acc[16][4];
    #pragma unroll
    for (int j = 0; j < 16; j++) { acc[j][0] = 0.f; acc[j][1] = 0.f; acc[j][2] = 0.f; acc[j][3] = 0.f; }

    int arow = tid >> 2, acol = (tid & 3) * 4;   // A: 256 chunks of 16B -> 1/thread

    // prefetch k-tile 0
    cp16(&sm[arow * ASTR + acol], Ag + (size_t)arow * D_ + acol);
    #pragma unroll
    for (int i = 0; i < 4; i++) {                // B: 1024 chunks each for hi/lo
        int c = tid + i * 256; int row = c >> 2, col = (c & 3) * 4;
        cp16(&sm[A_TILE + row * ASTR + col],          Bhg + (size_t)row * D_ + col);
        cp16(&sm[A_TILE + B_TILE + row * ASTR + col], Blg + (size_t)row * D_ + col);
    }
    asm volatile("cp.async.commit_group;");

    const int KI = D_ / BK;   // 32
    for (int kt = 0; kt < KI; kt++) {
        int buf = kt & 1;
        if (kt + 1 < KI) {
            int nb = buf ^ 1; int k0 = (kt + 1) * BK;
            float* base = sm + nb * BUF_SZ;
            cp16(&base[arow * ASTR + acol], Ag + (size_t)arow * D_ + k0 + acol);
            #pragma unroll
            for (int i = 0; i < 4; i++) {
                int c = tid + i * 256; int row = c >> 2, col = (c & 3) * 4;
                cp16(&base[A_TILE + row * ASTR + col],          Bhg + (size_t)row * D_ + k0 + col);
                cp16(&base[A_TILE + B_TILE + row * ASTR + col], Blg + (size_t)row * D_ + k0 + col);
            }
            asm volatile("cp.async.commit_group;");
            asm volatile("cp.async.wait_group 1;");
        } else {
            asm volatile("cp.async.wait_group 0;");
        }
        __syncthreads();

        const float* __restrict__ Ab  = sm + buf * BUF_SZ + (wm * 16) * ASTR;
        const float* __restrict__ Bh  = sm + buf * BUF_SZ + A_TILE + (wn * 128) * ASTR;
        const float* __restrict__ Bl  = Bh + B_TILE;
        #pragma unroll
        for (int s = 0; s < 2; s++) {           // two k8 steps per BK=16
            int kc = s * 8 + c4;
            // A fragment: split into tf32 hi/lo (only in-loop splits remaining)
            uint32_t ah[4], al[4];
            tf32_split(Ab[r4 * ASTR + kc],            ah[0], al[0]);
            tf32_split(Ab[(r4 + 8) * ASTR + kc],      ah[1], al[1]);
            tf32_split(Ab[r4 * ASTR + kc + 4],        ah[2], al[2]);
            tf32_split(Ab[(r4 + 8) * ASTR + kc + 4],  ah[3], al[3]);
            #pragma unroll
            for (int j = 0; j < 16; j++) {
                int ro = (j * 8 + r4) * ASTR + kc;
                uint32_t bh0 = __float_as_uint(Bh[ro]);
                uint32_t bh1 = __float_as_uint(Bh[ro + 4]);
                uint32_t bl0 = __float_as_uint(Bl[ro]);
                uint32_t bl1 = __float_as_uint(Bl[ro + 4]);
                // hi*hi + hi*lo + lo*hi  (lo*lo ~ 2^-24, dropped)
                mma_tf32(acc[j], ah[0], ah[1], ah[2], ah[3], bh0, bh1);
                mma_tf32(acc[j], ah[0], ah[1], ah[2], ah[3], bl0, bl1);
                mma_tf32(acc[j], al[0], al[1], al[2], al[3], bh0, bh1);
            }
        }
        __syncthreads();
    }

    // ---------------- fused epilogue ----------------
    float A0 = g_alpha[0], A1 = g_alpha[1], A2 = g_alpha[2];
    int gr0 = t0 + wm * 16 + r4;     // global t of this thread's first row
    int gr1 = gr0 + 8;
    const float* W0 = g_W + (size_t)gr0 * R_;
    const float* W1 = g_W + (size_t)gr1 * R_;

    float s0 = 0.f, s1 = 0.f;
    #pragma unroll
    for (int j = 0; j < 16; j++) {
        int col = wn * 128 + j * 8 + c4 * 2;
        float p;
        p = gphi(acc[j][0], A0, A1, A2) * W0[col];     acc[j][0] = p; s0 += p;
        p = gphi(acc[j][1], A0, A1, A2) * W0[col + 1]; acc[j][1] = p; s0 += p;
        p = gphi(acc[j][2], A0, A1, A2) * W1[col];     acc[j][2] = p; s1 += p;
        p = gphi(acc[j][3], A0, A1, A2) * W1[col + 1]; acc[j][3] = p; s1 += p;
    }
    // reduce across the 4 lanes sharing a row
    s0 += __shfl_xor_sync(0xffffffffu, s0, 1);
    s0 += __shfl_xor_sync(0xffffffffu, s0, 2);
    s1 += __shfl_xor_sync(0xffffffffu, s1, 1);
    s1 += __shfl_xor_sync(0xffffffffu, s1, 2);

    // reduce across the two warp_n halves
    __shared__ float red[4][2][16];
    if (c4 == 0) { red[wm][wn][r4] = s0; red[wm][wn][r4 + 8] = s1; }
    __syncthreads();
    float inv0 = 1.0f / fmaxf(red[wm][0][r4]     + red[wm][1][r4],     1e-6f);
    float inv1 = 1.0f / fmaxf(red[wm][0][r4 + 8] + red[wm][1][r4 + 8], 1e-6f);

    float* o0 = out + ((size_t)b * T_ + gr0) * (R_ + 1);
    float* o1 = out + ((size_t)b * T_ + gr1) * (R_ + 1);
    #pragma unroll
    for (int j = 0; j < 16; j++) {
        int col = wn * 128 + j * 8 + c4 * 2;
        o0[col]     = acc[j][0] * inv0;
        o0[col + 1] = acc[j][1] * inv0;
        o1[col]     = acc[j][2] * inv1;
        o1[col + 1] = acc[j][3] * inv1;
    }
    if (wn == 0 && c4 == 0) { o0[R_] = 1.0f; o1[R_] = 1.0f; }
}

// ---------------- launch ----------------
extern "C" void kernel_launch(void* const* d_in, const int* in_sizes, int n_in,
                              void* d_out, int out_size) {
    const float* z  = (const float*)d_in[0];
    const float* gw = (const float*)d_in[1];
    const float* ta = (const float*)d_in[2];
    float* out = (float*)d_out;

    prep_kernel<<<1, 256>>>(gw, ta);
    w_kernel<<<T_, R_>>>();
    norm_kernel<<<B_ * T_, 128>>>(z);
    gather_kernel<<<B_ * R_, 128>>>();

    cudaFuncSetAttribute(gemm_kernel, cudaFuncAttributeMaxDynamicSharedMemorySize, SMEM_BYTES);
    gemm_kernel<<<dim3(T_ / BM, B_), 256, SMEM_BYTES>>>(out);
}